// round 15
// baseline (speedup 1.0000x reference)
#include <cuda_runtime.h>
#include <cuda_fp16.h>
#include <math.h>
#include <stdint.h>

// Problem constants
#define BATCH 2
#define SEQ   2048
#define DMODEL 2048
#define NHEADS 16
#define DHEAD 128
#define MROWS (BATCH*SEQ)          // 4096
#define KDIM  DMODEL

// -------------------- scratch (static device globals; no allocation) ------
__device__ __align__(16) __half g_xh[MROWS * DMODEL];
__device__ __align__(16) __half g_wq[DMODEL * DMODEL];
__device__ __align__(16) __half g_wk[DMODEL * DMODEL];
__device__ __align__(16) __half g_wv[DMODEL * DMODEL];
__device__ __align__(16) __half g_wo[DMODEL * DMODEL];
__device__ __align__(16) __half g_qh[MROWS * DMODEL];
__device__ __align__(16) __half g_kh[MROWS * DMODEL];
__device__ __align__(16) __half g_vh[MROWS * DMODEL];
__device__ __align__(16) __half g_att[MROWS * DMODEL];

// ============================ PTX helpers ==================================
__device__ __forceinline__ uint32_t smem_u32(const void* p) {
    uint32_t a;
    asm("{ .reg .u64 t; cvta.to.shared.u64 t, %1; cvt.u32.u64 %0, t; }" : "=r"(a) : "l"(p));
    return a;
}
#define CP_ASYNC16(dst, src) \
    asm volatile("cp.async.cg.shared.global [%0], [%1], 16;" :: "r"(dst), "l"(src))
#define CP_COMMIT() asm volatile("cp.async.commit_group;" ::: "memory")
#define CP_WAIT(n)  asm volatile("cp.async.wait_group %0;" :: "n"(n) : "memory")

#define LDSM4(r0, r1, r2, r3, addr) \
    asm volatile("ldmatrix.sync.aligned.m8n8.x4.shared.b16 {%0,%1,%2,%3}, [%4];" \
        : "=r"(r0), "=r"(r1), "=r"(r2), "=r"(r3) : "r"(addr))
#define LDSM4T(r0, r1, r2, r3, addr) \
    asm volatile("ldmatrix.sync.aligned.m8n8.x4.trans.shared.b16 {%0,%1,%2,%3}, [%4];" \
        : "=r"(r0), "=r"(r1), "=r"(r2), "=r"(r3) : "r"(addr))

#define MMA16816(c, a, b) \
    asm volatile("mma.sync.aligned.m16n8k16.row.col.f32.f16.f16.f32 " \
        "{%0,%1,%2,%3},{%4,%5,%6,%7},{%8,%9},{%0,%1,%2,%3};" \
        : "+f"((c)[0]), "+f"((c)[1]), "+f"((c)[2]), "+f"((c)[3]) \
        : "r"((a)[0]), "r"((a)[1]), "r"((a)[2]), "r"((a)[3]), "r"((b)[0]), "r"((b)[1]))

__device__ __forceinline__ uint32_t pk16(__half a, __half b) {
    return (uint32_t)__half_as_ushort(a) | ((uint32_t)__half_as_ushort(b) << 16);
}

// ============================================================================
// pack_all: one launch converts x + 4 weights fp32->fp16; 4 pairs/thread.
// ============================================================================
#define NPX (MROWS * DMODEL / 2)
#define NPW (DMODEL * DMODEL / 2)
#define NP_TOTAL (NPX + 4 * NPW)

__global__ __launch_bounds__(256)
void pack_all(const float* __restrict__ x,
              const float* __restrict__ Wq, const float* __restrict__ Wk,
              const float* __restrict__ Wv, const float* __restrict__ Wo,
              uint32_t* __restrict__ xh,
              uint32_t* __restrict__ wq, uint32_t* __restrict__ wk,
              uint32_t* __restrict__ wv, uint32_t* __restrict__ wo)
{
    int i0 = blockIdx.x * 1024 + threadIdx.x;
#pragma unroll
    for (int t = 0; t < 4; t++) {
        int i = i0 + t * 256;
        if (i >= NP_TOTAL) return;
        const float* src; uint32_t* dst; int off;
        if (i < NPX)                { src = x;  dst = xh; off = i; }
        else if (i < NPX + NPW)     { src = Wq; dst = wq; off = i - NPX; }
        else if (i < NPX + 2*NPW)   { src = Wk; dst = wk; off = i - NPX - NPW; }
        else if (i < NPX + 3*NPW)   { src = Wv; dst = wv; off = i - NPX - 2*NPW; }
        else                        { src = Wo; dst = wo; off = i - NPX - 3*NPW; }
        float2 v = ((const float2*)src)[off];
        dst[off] = pk16(__float2half(v.x), __float2half(v.y));
    }
}

// ============================================================================
// gemm mainloop core: C_z = A @ B_z^T, fp16 operands, fp32 accumulate.
// R15: 16 warps as 4m x 2n (warp tile 32x64, 2.67 MMA/LDSM),
//      3 stages x 32KB -> single __syncthreads per k-iteration.
// ============================================================================
#define BKD 64
#define TILE_B   (128 * BKD * 2)              // 16 KB per plane
#define STG1_B   (2 * TILE_B)                 // 32 KB (A, B)
#define GNSTAGE  3
#define G1_SMEM  (GNSTAGE * STG1_B)           // 96 KB (>= 64KB fp32 stage)

#define GEMM1_BODY                                                                   \
    extern __shared__ char smc[];                                                    \
    const uint32_t sb = smem_u32(smc);                                               \
    const int tid  = threadIdx.x;                                                    \
    const int lane = tid & 31;                                                       \
    const int wid  = tid >> 5;                                                       \
    const int wm   = wid & 3;          /* 4 m-tiles of 32 */                         \
    const int wn   = wid >> 2 & 1;     /* 2 n-tiles of 64 */                         \
    const int wpair = wid >> 3;        /* 2 replicas along m? no: 16 warps = 4x2x2 */\
    const int m0   = blockIdx.y * 128;                                               \
    const int n0   = blockIdx.x * 128;                                               \
    const int rA = tid >> 3, cA = tid & 7;                                           \
    const int rB = (tid + 512) >> 3, cB = (tid + 512) & 7;                           \
    const uint32_t dA = (uint32_t)(rA * 128 + ((cA ^ (rA & 7)) << 4));               \
    const uint32_t dB = (uint32_t)(rB * 128 + ((cB ^ (rB & 7)) << 4));               \
    const __half* srcA = A + (size_t)m0 * KDIM;                                      \
    const __half* srcB = B + (size_t)n0 * KDIM;                                      \
    auto load_stage = [&](int s, int kb) {                                           \
        uint32_t base = sb + s * STG1_B;                                             \
        int koff = kb * BKD;                                                         \
        CP_ASYNC16(base + dA,          srcA + (size_t)rA * KDIM + koff + cA * 8);    \
        CP_ASYNC16(base + dB,          srcA + (size_t)rB * KDIM + koff + cB * 8);    \
        CP_ASYNC16(base + TILE_B + dA, srcB + (size_t)rA * KDIM + koff + cA * 8);    \
        CP_ASYNC16(base + TILE_B + dB, srcB + (size_t)rB * KDIM + koff + cB * 8);    \
    };                                                                               \
    float acc[2][8][4];                                                              \
    _Pragma("unroll")                                                                \
    for (int i = 0; i < 2; i++)                                                      \
        for (int j = 0; j < 8; j++)                                                  \
            for (int r = 0; r < 4; r++) acc[i][j][r] = 0.f;                          \
    load_stage(0, 0); CP_COMMIT();                                                   \
    load_stage(1, 1); CP_COMMIT();                                                   \
    const int arow = wm * 32 + (lane & 15);                                          \
    const int lhalf = lane >> 4;                                                     \
    const int NKB = KDIM / BKD;                                                      \
    /* 16 warps: wid = wm(0..3) + 4*wn(0..1) + 8*ks_half(0..1): split ks range */    \
    const int ksh = wid >> 3;   /* 0..1: each half of warps handles 2 of 4 ks */     \
    (void)wpair;                                                                     \
    for (int kc = 0; kc < NKB; kc++) {                                               \
        CP_WAIT(1);                                                                  \
        __syncthreads();                                                             \
        if (kc + 2 < NKB) { load_stage((kc + 2) % GNSTAGE, kc + 2); CP_COMMIT(); }   \
        else              { CP_COMMIT(); }                                           \
        uint32_t base = sb + (kc % GNSTAGE) * STG1_B;                                \
        uint32_t aB = base, bB = base + TILE_B;                                      \
        _Pragma("unroll")                                                            \
        for (int ksq = 0; ksq < 2; ksq++) {                                          \
            int ks = ksh * 2 + ksq;                                                  \
            uint32_t ah[2][4], bh[8][2];                                             \
            _Pragma("unroll")                                                        \
            for (int i = 0; i < 2; i++) {                                            \
                int row = arow + i * 16;                                             \
                uint32_t off = (uint32_t)(row * 128 + (((ks * 2 + lhalf) ^ (row & 7)) << 4)); \
                LDSM4(ah[i][0], ah[i][1], ah[i][2], ah[i][3], aB + off);             \
            }                                                                        \
            _Pragma("unroll")                                                        \
            for (int jp = 0; jp < 4; jp++) {                                         \
                int row = wn * 64 + jp * 16 + (lane & 15);                           \
                uint32_t off = (uint32_t)(row * 128 + (((ks * 2 + lhalf) ^ (row & 7)) << 4)); \
                uint32_t r0, r1_, r2_, r3_;                                          \
                LDSM4(r0, r1_, r2_, r3_, bB + off);                                  \
                bh[2 * jp][0] = r0;  bh[2 * jp][1] = r2_;                            \
                bh[2 * jp + 1][0] = r1_; bh[2 * jp + 1][1] = r3_;                    \
            }                                                                        \
            _Pragma("unroll")                                                        \
            for (int i = 0; i < 2; i++)                                              \
                for (int j = 0; j < 8; j++)                                          \
                    MMA16816(acc[i][j], ah[i], bh[j]);                               \
        }                                                                            \
    }                                                                                \
    __syncthreads();

// NOTE on layout: 16 warps = (wm 0..3) x (wn 0..1) x (ksh 0..1). Each (wm,wn)
// pair is covered by TWO warps that each process half of the ks range per kc;
// their partial sums live in separate accumulators and are combined in the
// epilogue via the fp32 staging buffer (atomic-free: disjoint ks => sum).

__device__ __forceinline__ void stage_acc_sum(float* stg, int wm, int wn, int ksh,
                                              int lane, float acc[2][8][4], int tid)
{
    // first replica (ksh==0) writes, second adds — ordered by barrier.
#pragma unroll
    for (int pass = 0; pass < 2; pass++) {
        if (ksh == pass) {
#pragma unroll
            for (int i = 0; i < 2; i++)
#pragma unroll
                for (int j = 0; j < 8; j++) {
                    int ml = wm * 32 + i * 16 + (lane >> 2);
                    int nl = wn * 64 + j * 8 + (lane & 3) * 2;
                    if (pass == 0) {
                        stg[ml * 128 + nl]           = acc[i][j][0];
                        stg[ml * 128 + nl + 1]       = acc[i][j][1];
                        stg[(ml + 8) * 128 + nl]     = acc[i][j][2];
                        stg[(ml + 8) * 128 + nl + 1] = acc[i][j][3];
                    } else {
                        stg[ml * 128 + nl]           += acc[i][j][0];
                        stg[ml * 128 + nl + 1]       += acc[i][j][1];
                        stg[(ml + 8) * 128 + nl]     += acc[i][j][2];
                        stg[(ml + 8) * 128 + nl + 1] += acc[i][j][3];
                    }
                }
        }
        __syncthreads();
    }
}

// ============================================================================
// gemm_qkv: QKV projection with rope fused into epilogue (fp32 staging).
// z==0: q (rope + 1/sqrt(dh)); z==1: k (rope); z==2: v (plain convert).
// ============================================================================
__global__ __launch_bounds__(512)
void gemm_qkv(const __half* __restrict__ A,
              const __half* __restrict__ B0, const __half* __restrict__ B1,
              const __half* __restrict__ B2,
              __half* __restrict__ C0, __half* __restrict__ C1, __half* __restrict__ C2,
              const float* __restrict__ rc, const float* __restrict__ rs)
{
    const int z = blockIdx.z;
    const __half* B = (z == 0) ? B0 : (z == 1) ? B1 : B2;
    __half* C = (z == 0) ? C0 : (z == 1) ? C1 : C2;

    GEMM1_BODY

    float* stg = (float*)smc;
    stage_acc_sum(stg, wm, wn, ksh, lane, acc, tid);

    if (z == 2) {
#pragma unroll
        for (int it = 0; it < 8; it++) {
            int idx = tid + it * 512;
            int row = idx >> 5;
            int q4 = (idx & 31) * 4;
            float4 v = *(float4*)&stg[row * 128 + q4];
            __half* Cp = C + (size_t)(m0 + row) * DMODEL + n0 + q4;
            *(uint32_t*)&Cp[0] = pk16(__float2half(v.x), __float2half(v.y));
            *(uint32_t*)&Cp[2] = pk16(__float2half(v.z), __float2half(v.w));
        }
    } else {
        const float qs = (z == 0) ? 0.088388347648318447f : 1.0f;
#pragma unroll
        for (int it = 0; it < 4; it++) {
            int idx = tid + it * 512;
            int row = idx >> 4;
            int d = (idx & 15) * 4;
            int spos = (m0 + row) & (SEQ - 1);
            float4 lo = *(float4*)&stg[row * 128 + d];
            float4 hi = *(float4*)&stg[row * 128 + 64 + d];
            float4 c0 = *(const float4*)&rc[spos * DHEAD + d];
            float4 s0 = *(const float4*)&rs[spos * DHEAD + d];
            float4 c1 = *(const float4*)&rc[spos * DHEAD + 64 + d];
            float4 s1 = *(const float4*)&rs[spos * DHEAD + 64 + d];
            float l0 = (lo.x * c0.x - hi.x * s0.x) * qs;
            float l1 = (lo.y * c0.y - hi.y * s0.y) * qs;
            float l2 = (lo.z * c0.z - hi.z * s0.z) * qs;
            float l3 = (lo.w * c0.w - hi.w * s0.w) * qs;
            float u0 = (hi.x * c1.x + lo.x * s1.x) * qs;
            float u1 = (hi.y * c1.y + lo.y * s1.y) * qs;
            float u2 = (hi.z * c1.z + lo.z * s1.z) * qs;
            float u3 = (hi.w * c1.w + lo.w * s1.w) * qs;
            __half* Cp = C + (size_t)(m0 + row) * DMODEL + n0 + d;
            *(uint32_t*)&Cp[0]  = pk16(__float2half(l0), __float2half(l1));
            *(uint32_t*)&Cp[2]  = pk16(__float2half(l2), __float2half(l3));
            *(uint32_t*)&Cp[64] = pk16(__float2half(u0), __float2half(u1));
            *(uint32_t*)&Cp[66] = pk16(__float2half(u2), __float2half(u3));
        }
    }
}

// ============================================================================
// gemm_1p_f: plain fp16 GEMM, fp32 output (final projection).
// ============================================================================
__global__ __launch_bounds__(512)
void gemm_1p_f(const __half* __restrict__ A, const __half* __restrict__ B,
               float* __restrict__ C)
{
    GEMM1_BODY

    float* stg = (float*)smc;
    stage_acc_sum(stg, wm, wn, ksh, lane, acc, tid);

#pragma unroll
    for (int it = 0; it < 8; it++) {
        int idx = tid + it * 512;
        int row = idx >> 5;
        int q4 = (idx & 31) * 4;
        float4 v = *(float4*)&stg[row * 128 + q4];
        *(float4*)&C[(size_t)(m0 + row) * DMODEL + n0 + q4] = v;
    }
}

// ============================================================================
// attn_tc: flash attention (unchanged R13/R14).
// ============================================================================
#define NKT (SEQ/64)
#define ATT_PLANE_B 16384
#define ATT_STAGE_B (2*ATT_PLANE_B)
#define ATT_Q_B     32768
#define ATT_NSTAGE  3
#define ATT_TC_SMEM (ATT_Q_B + ATT_NSTAGE*ATT_STAGE_B)   // 131072

__global__ __launch_bounds__(256, 1)
void attn_tc(const __half* __restrict__ qh,
             const __half* __restrict__ khi,
             const __half* __restrict__ vhi,
             __half* __restrict__ oh)
{
    extern __shared__ char smc[];
    const uint32_t sb = smem_u32(smc);
    const uint32_t QH = sb;
    const uint32_t ST = sb + ATT_Q_B;

    const int tid = threadIdx.x;
    const int lane = tid & 31;
    const int wid = tid >> 5;
    const int b = blockIdx.z, h = blockIdx.y;
    const int q0 = blockIdx.x * 128;
    const int wrow = wid * 16;

    {
        const __half* src0 = qh + ((size_t)(b * SEQ + q0)) * DMODEL + h * DHEAD;
#pragma unroll
        for (int i = 0; i < 8; i++) {
            int idx = tid + i * 256;
            int row = idx >> 4, ch = idx & 15;
            uint32_t dst = QH + row * 256 + ((ch ^ (row & 15)) << 4);
            CP_ASYNC16(dst, src0 + (size_t)row * DMODEL + ch * 8);
        }
    }

    const __half* pl[2] = { khi, vhi };
    auto load_kv = [&](int st, int kt) {
        uint32_t base = ST + st * ATT_STAGE_B;
#pragma unroll
        for (int i = 0; i < 8; i++) {
            int idx = tid + i * 256;
            int p = idx >> 10;
            int c = idx & 1023;
            int row = c >> 4, ch = c & 15;
            const __half* src = pl[p] +
                ((size_t)(b * SEQ + kt * 64 + row)) * DMODEL + h * DHEAD + ch * 8;
            uint32_t dst = base + p * ATT_PLANE_B + row * 256 + ((ch ^ (row & 15)) << 4);
            CP_ASYNC16(dst, src);
        }
    };

    float o_[16][4];
#pragma unroll
    for (int n = 0; n < 16; n++)
#pragma unroll
        for (int r = 0; r < 4; r++) o_[n][r] = 0.f;
    float m_a = -3.0e38f, m_b = -3.0e38f, l_a = 0.f, l_b = 0.f;

    load_kv(0, 0); CP_COMMIT();
    load_kv(1, 1); CP_COMMIT();

    const int qrow = wrow + (lane & 15);
    const int lh = lane >> 4;

    int st = 0;
    for (int kt = 0; kt < NKT; kt++) {
        CP_WAIT(1);
        __syncthreads();
        uint32_t bs = ST + st * ATT_STAGE_B;

        if (kt + 2 < NKT) {
            int st2 = st + 2; if (st2 >= ATT_NSTAGE) st2 -= ATT_NSTAGE;
            load_kv(st2, kt + 2); CP_COMMIT();
        } else {
            CP_COMMIT();
        }

        float s[8][4];
#pragma unroll
        for (int j = 0; j < 8; j++)
#pragma unroll
            for (int r = 0; r < 4; r++) s[j][r] = 0.f;

#pragma unroll
        for (int ks = 0; ks < 8; ks++) {
            uint32_t qoff = (uint32_t)(qrow * 256 + (((ks * 2 + lh) ^ (qrow & 15)) << 4));
            uint32_t ah[4];
            LDSM4(ah[0], ah[1], ah[2], ah[3], QH + qoff);
#pragma unroll
            for (int nb = 0; nb < 4; nb++) {
                int krow = nb * 16 + (lane & 15);
                uint32_t koff = (uint32_t)(krow * 256 + (((ks * 2 + lh) ^ (krow & 15)) << 4));
                uint32_t h0, h1, h2, h3;
                LDSM4(h0, h1, h2, h3, bs + koff);
                uint32_t bh0[2] = { h0, h2 }, bh1[2] = { h1, h3 };
                MMA16816(s[2*nb],   ah, bh0);
                MMA16816(s[2*nb+1], ah, bh1);
            }
        }

        float mla = -3.0e38f, mlb = -3.0e38f;
#pragma unroll
        for (int j = 0; j < 8; j++) {
            mla = fmaxf(mla, fmaxf(s[j][0], s[j][1]));
            mlb = fmaxf(mlb, fmaxf(s[j][2], s[j][3]));
        }
        mla = fmaxf(mla, __shfl_xor_sync(0xffffffffu, mla, 1));
        mla = fmaxf(mla, __shfl_xor_sync(0xffffffffu, mla, 2));
        mlb = fmaxf(mlb, __shfl_xor_sync(0xffffffffu, mlb, 1));
        mlb = fmaxf(mlb, __shfl_xor_sync(0xffffffffu, mlb, 2));
        float mna = fmaxf(m_a, mla), mnb = fmaxf(m_b, mlb);
        float aa = __expf(m_a - mna), ab = __expf(m_b - mnb);

        uint32_t pAh[8], pBh[8];
        float sa = 0.f, sb2 = 0.f;
#pragma unroll
        for (int j = 0; j < 8; j++) {
            float p0 = __expf(s[j][0] - mna), p1 = __expf(s[j][1] - mna);
            float p2 = __expf(s[j][2] - mnb), p3 = __expf(s[j][3] - mnb);
            sa += p0 + p1; sb2 += p2 + p3;
            pAh[j] = pk16(__float2half(p0), __float2half(p1));
            pBh[j] = pk16(__float2half(p2), __float2half(p3));
        }
        sa  += __shfl_xor_sync(0xffffffffu, sa, 1);
        sa  += __shfl_xor_sync(0xffffffffu, sa, 2);
        sb2 += __shfl_xor_sync(0xffffffffu, sb2, 1);
        sb2 += __shfl_xor_sync(0xffffffffu, sb2, 2);
        m_a = mna; m_b = mnb;
        l_a = l_a * aa + sa; l_b = l_b * ab + sb2;

#pragma unroll
        for (int n = 0; n < 16; n++) {
            o_[n][0] *= aa; o_[n][1] *= aa; o_[n][2] *= ab; o_[n][3] *= ab;
        }

#pragma unroll
        for (int kp = 0; kp < 4; kp++) {
            uint32_t ah4[4] = { pAh[2*kp], pBh[2*kp], pAh[2*kp+1], pBh[2*kp+1] };
            int vrow = kp * 16 + (lane & 15);
#pragma unroll
            for (int nb = 0; nb < 8; nb++) {
                uint32_t ch = (uint32_t)(nb * 2 + lh);
                uint32_t voff = (uint32_t)(vrow * 256 + ((ch ^ (vrow & 15)) << 4));
                uint32_t h0, h1, h2, h3;
                LDSM4T(h0, h1, h2, h3, bs + ATT_PLANE_B + voff);
                uint32_t bh0[2] = { h0, h1 }, bh1[2] = { h2, h3 };
                MMA16816(o_[2*nb],   ah4, bh0);
                MMA16816(o_[2*nb+1], ah4, bh1);
            }
        }

        if (++st == ATT_NSTAGE) st = 0;
    }

    float ia = 1.f / l_a, ib = 1.f / l_b;
    size_t r0 = (size_t)(b * SEQ + q0 + wrow + (lane >> 2)) * DMODEL + h * DHEAD + 2 * (lane & 3);
    size_t r1 = r0 + (size_t)8 * DMODEL;
#pragma unroll
    for (int n = 0; n < 16; n++) {
        *(uint32_t*)&oh[r0 + n*8] = pk16(__float2half(o_[n][0] * ia), __float2half(o_[n][1] * ia));
        *(uint32_t*)&oh[r1 + n*8] = pk16(__float2half(o_[n][2] * ib), __float2half(o_[n][3] * ib));
    }
}

// ============================================================================
extern "C" void kernel_launch(void* const* d_in, const int* in_sizes, int n_in,
                              void* d_out, int out_size)
{
    const float* x  = (const float*)d_in[0];
    const float* rc = (const float*)d_in[1];
    const float* rs = (const float*)d_in[2];
    const float* Wq = (const float*)d_in[3];
    const float* Wk = (const float*)d_in[4];
    const float* Wv = (const float*)d_in[5];
    const float* Wo = (const float*)d_in[6];
    float* out = (float*)d_out;

    __half *xh, *wq, *wk, *wv, *wo, *qhp, *khp, *vhp, *att;
    cudaGetSymbolAddress((void**)&xh, g_xh);
    cudaGetSymbolAddress((void**)&wq, g_wq);     cudaGetSymbolAddress((void**)&wk, g_wk);
    cudaGetSymbolAddress((void**)&wv, g_wv);     cudaGetSymbolAddress((void**)&wo, g_wo);
    cudaGetSymbolAddress((void**)&qhp, g_qh);    cudaGetSymbolAddress((void**)&khp, g_kh);
    cudaGetSymbolAddress((void**)&vhp, g_vh);
    cudaGetSymbolAddress((void**)&att, g_att);

    cudaFuncSetAttribute(gemm_qkv,  cudaFuncAttributeMaxDynamicSharedMemorySize, G1_SMEM);
    cudaFuncSetAttribute(gemm_1p_f, cudaFuncAttributeMaxDynamicSharedMemorySize, G1_SMEM);
    cudaFuncSetAttribute(attn_tc,   cudaFuncAttributeMaxDynamicSharedMemorySize, ATT_TC_SMEM);

    pack_all<<<(NP_TOTAL + 1023) / 1024, 256>>>(
        x, Wq, Wk, Wv, Wo,
        (uint32_t*)xh, (uint32_t*)wq, (uint32_t*)wk, (uint32_t*)wv, (uint32_t*)wo);

    gemm_qkv<<<dim3(DMODEL / 128, MROWS / 128, 3), 512, G1_SMEM>>>(
        xh, wq, wk, wv, qhp, khp, vhp, rc, rs);

    attn_tc<<<dim3(SEQ / 128, NHEADS, BATCH), 256, ATT_TC_SMEM>>>(qhp, khp, vhp, att);

    gemm_1p_f<<<dim3(DMODEL / 128, MROWS / 128, 1), 512, G1_SMEM>>>(att, wo, out);
}

// round 16
// speedup vs baseline: 1.1742x; 1.1742x over previous
#include <cuda_runtime.h>
#include <cuda_fp16.h>
#include <math.h>
#include <stdint.h>

// Problem constants
#define BATCH 2
#define SEQ   2048
#define DMODEL 2048
#define NHEADS 16
#define DHEAD 128
#define MROWS (BATCH*SEQ)          // 4096
#define KDIM  DMODEL

// -------------------- scratch (static device globals; no allocation) ------
__device__ __align__(16) __half g_xh[MROWS * DMODEL];
__device__ __align__(16) __half g_wq[DMODEL * DMODEL];
__device__ __align__(16) __half g_wk[DMODEL * DMODEL];
__device__ __align__(16) __half g_wv[DMODEL * DMODEL];
__device__ __align__(16) __half g_wo[DMODEL * DMODEL];
__device__ __align__(16) __half g_qh[MROWS * DMODEL];
__device__ __align__(16) __half g_kh[MROWS * DMODEL];
__device__ __align__(16) __half g_vh[MROWS * DMODEL];
__device__ __align__(16) __half g_att[MROWS * DMODEL];

// ============================ PTX helpers ==================================
__device__ __forceinline__ uint32_t smem_u32(const void* p) {
    uint32_t a;
    asm("{ .reg .u64 t; cvta.to.shared.u64 t, %1; cvt.u32.u64 %0, t; }" : "=r"(a) : "l"(p));
    return a;
}
#define CP_ASYNC16(dst, src) \
    asm volatile("cp.async.cg.shared.global [%0], [%1], 16;" :: "r"(dst), "l"(src))
#define CP_COMMIT() asm volatile("cp.async.commit_group;" ::: "memory")
#define CP_WAIT(n)  asm volatile("cp.async.wait_group %0;" :: "n"(n) : "memory")

#define LDSM4(r0, r1, r2, r3, addr) \
    asm volatile("ldmatrix.sync.aligned.m8n8.x4.shared.b16 {%0,%1,%2,%3}, [%4];" \
        : "=r"(r0), "=r"(r1), "=r"(r2), "=r"(r3) : "r"(addr))
#define LDSM4T(r0, r1, r2, r3, addr) \
    asm volatile("ldmatrix.sync.aligned.m8n8.x4.trans.shared.b16 {%0,%1,%2,%3}, [%4];" \
        : "=r"(r0), "=r"(r1), "=r"(r2), "=r"(r3) : "r"(addr))

#define MMA16816(c, a, b) \
    asm volatile("mma.sync.aligned.m16n8k16.row.col.f32.f16.f16.f32 " \
        "{%0,%1,%2,%3},{%4,%5,%6,%7},{%8,%9},{%0,%1,%2,%3};" \
        : "+f"((c)[0]), "+f"((c)[1]), "+f"((c)[2]), "+f"((c)[3]) \
        : "r"((a)[0]), "r"((a)[1]), "r"((a)[2]), "r"((a)[3]), "r"((b)[0]), "r"((b)[1]))

__device__ __forceinline__ uint32_t pk16(__half a, __half b) {
    return (uint32_t)__half_as_ushort(a) | ((uint32_t)__half_as_ushort(b) << 16);
}

// ============================================================================
// pack_all: one launch converts x + 4 weights fp32->fp16; 4 pairs/thread.
// ============================================================================
#define NPX (MROWS * DMODEL / 2)
#define NPW (DMODEL * DMODEL / 2)
#define NP_TOTAL (NPX + 4 * NPW)

__global__ __launch_bounds__(256)
void pack_all(const float* __restrict__ x,
              const float* __restrict__ Wq, const float* __restrict__ Wk,
              const float* __restrict__ Wv, const float* __restrict__ Wo,
              uint32_t* __restrict__ xh,
              uint32_t* __restrict__ wq, uint32_t* __restrict__ wk,
              uint32_t* __restrict__ wv, uint32_t* __restrict__ wo)
{
    int i0 = blockIdx.x * 1024 + threadIdx.x;
#pragma unroll
    for (int t = 0; t < 4; t++) {
        int i = i0 + t * 256;
        if (i >= NP_TOTAL) return;
        const float* src; uint32_t* dst; int off;
        if (i < NPX)                { src = x;  dst = xh; off = i; }
        else if (i < NPX + NPW)     { src = Wq; dst = wq; off = i - NPX; }
        else if (i < NPX + 2*NPW)   { src = Wk; dst = wk; off = i - NPX - NPW; }
        else if (i < NPX + 3*NPW)   { src = Wv; dst = wv; off = i - NPX - 2*NPW; }
        else                        { src = Wo; dst = wo; off = i - NPX - 3*NPW; }
        float2 v = ((const float2*)src)[off];
        dst[off] = pk16(__float2half(v.x), __float2half(v.y));
    }
}

// ============================================================================
// gemm mainloop core (R14 form): 16 warps 4m x 4n (warp tile 32x32), BKD=64,
// 2 stages x 32KB. fp16 operands, fp32 accumulate.
// ============================================================================
#define BKD 64
#define TILE_B   (128 * BKD * 2)              // 16 KB per plane
#define STG1_B   (2 * TILE_B)                 // 32 KB (A, B)
#define G1_SMEM  (2 * STG1_B)                 // 64 KB (also = 128x128 fp32 stage)

#define GEMM1_BODY                                                                   \
    extern __shared__ char smc[];                                                    \
    const uint32_t sb = smem_u32(smc);                                               \
    const int tid  = threadIdx.x;                                                    \
    const int lane = tid & 31;                                                       \
    const int wid  = tid >> 5;                                                       \
    const int wm   = wid & 3;                                                        \
    const int wn   = wid >> 2;                                                       \
    const int m0   = blockIdx.y * 128;                                               \
    const int n0   = blockIdx.x * 128;                                               \
    const int rA = tid >> 3, cA = tid & 7;                                           \
    const int rB = (tid + 512) >> 3, cB = (tid + 512) & 7;                           \
    const uint32_t dA = (uint32_t)(rA * 128 + ((cA ^ (rA & 7)) << 4));               \
    const uint32_t dB = (uint32_t)(rB * 128 + ((cB ^ (rB & 7)) << 4));               \
    const __half* srcA = A + (size_t)m0 * KDIM;                                      \
    const __half* srcB = B + (size_t)n0 * KDIM;                                      \
    auto load_stage = [&](int s, int kb) {                                           \
        uint32_t base = sb + s * STG1_B;                                             \
        int koff = kb * BKD;                                                         \
        CP_ASYNC16(base + dA,          srcA + (size_t)rA * KDIM + koff + cA * 8);    \
        CP_ASYNC16(base + dB,          srcA + (size_t)rB * KDIM + koff + cB * 8);    \
        CP_ASYNC16(base + TILE_B + dA, srcB + (size_t)rA * KDIM + koff + cA * 8);    \
        CP_ASYNC16(base + TILE_B + dB, srcB + (size_t)rB * KDIM + koff + cB * 8);    \
    };                                                                               \
    float acc[2][4][4];                                                              \
    _Pragma("unroll")                                                                \
    for (int i = 0; i < 2; i++)                                                      \
        for (int j = 0; j < 4; j++)                                                  \
            for (int r = 0; r < 4; r++) acc[i][j][r] = 0.f;                          \
    load_stage(0, 0); CP_COMMIT();                                                   \
    const int arow = wm * 32 + (lane & 15);                                          \
    const int bnrow = wn * 32 + (lane & 15);                                         \
    const int lhalf = lane >> 4;                                                     \
    const int NKB = KDIM / BKD;                                                      \
    for (int kc = 0; kc < NKB; kc++) {                                               \
        if (kc + 1 < NKB) { load_stage((kc + 1) & 1, kc + 1); CP_COMMIT(); CP_WAIT(1); } \
        else              { CP_WAIT(0); }                                            \
        __syncthreads();                                                             \
        uint32_t base = sb + (kc & 1) * STG1_B;                                      \
        uint32_t aB = base, bB = base + TILE_B;                                      \
        _Pragma("unroll")                                                            \
        for (int ks = 0; ks < 4; ks++) {                                             \
            uint32_t ah[2][4], bh[4][2];                                             \
            _Pragma("unroll")                                                        \
            for (int i = 0; i < 2; i++) {                                            \
                int row = arow + i * 16;                                             \
                uint32_t off = (uint32_t)(row * 128 + (((ks * 2 + lhalf) ^ (row & 7)) << 4)); \
                LDSM4(ah[i][0], ah[i][1], ah[i][2], ah[i][3], aB + off);             \
            }                                                                        \
            _Pragma("unroll")                                                        \
            for (int jp = 0; jp < 2; jp++) {                                         \
                int row = bnrow + jp * 16;                                           \
                uint32_t off = (uint32_t)(row * 128 + (((ks * 2 + lhalf) ^ (row & 7)) << 4)); \
                uint32_t r0, r1_, r2_, r3_;                                          \
                LDSM4(r0, r1_, r2_, r3_, bB + off);                                  \
                bh[2 * jp][0] = r0;  bh[2 * jp][1] = r2_;                            \
                bh[2 * jp + 1][0] = r1_; bh[2 * jp + 1][1] = r3_;                    \
            }                                                                        \
            _Pragma("unroll")                                                        \
            for (int i = 0; i < 2; i++)                                              \
                for (int j = 0; j < 4; j++)                                          \
                    MMA16816(acc[i][j], ah[i], bh[j]);                               \
        }                                                                            \
        __syncthreads();                                                             \
    }

// ============================================================================
// gemm_qkv: QKV projection with rope fused into epilogue (fp32 staging).
// z==0: q (rope + 1/sqrt(dh)); z==1: k (rope); z==2: v (plain convert).
// ============================================================================
__global__ __launch_bounds__(512)
void gemm_qkv(const __half* __restrict__ A,
              const __half* __restrict__ B0, const __half* __restrict__ B1,
              const __half* __restrict__ B2,
              __half* __restrict__ C0, __half* __restrict__ C1, __half* __restrict__ C2,
              const float* __restrict__ rc, const float* __restrict__ rs)
{
    const int z = blockIdx.z;
    const __half* B = (z == 0) ? B0 : (z == 1) ? B1 : B2;
    __half* C = (z == 0) ? C0 : (z == 1) ? C1 : C2;

    GEMM1_BODY

    float* stg = (float*)smc;
#pragma unroll
    for (int i = 0; i < 2; i++)
#pragma unroll
        for (int j = 0; j < 4; j++) {
            int ml = wm * 32 + i * 16 + (lane >> 2);
            int nl = wn * 32 + j * 8 + (lane & 3) * 2;
            stg[ml * 128 + nl]           = acc[i][j][0];
            stg[ml * 128 + nl + 1]       = acc[i][j][1];
            stg[(ml + 8) * 128 + nl]     = acc[i][j][2];
            stg[(ml + 8) * 128 + nl + 1] = acc[i][j][3];
        }
    __syncthreads();

    if (z == 2) {
#pragma unroll
        for (int it = 0; it < 8; it++) {
            int idx = tid + it * 512;
            int row = idx >> 5;
            int q4 = (idx & 31) * 4;
            float4 v = *(float4*)&stg[row * 128 + q4];
            __half* Cp = C + (size_t)(m0 + row) * DMODEL + n0 + q4;
            *(uint32_t*)&Cp[0] = pk16(__float2half(v.x), __float2half(v.y));
            *(uint32_t*)&Cp[2] = pk16(__float2half(v.z), __float2half(v.w));
        }
    } else {
        const float qs = (z == 0) ? 0.088388347648318447f : 1.0f;
#pragma unroll
        for (int it = 0; it < 4; it++) {
            int idx = tid + it * 512;
            int row = idx >> 4;
            int d = (idx & 15) * 4;
            int spos = (m0 + row) & (SEQ - 1);
            float4 lo = *(float4*)&stg[row * 128 + d];
            float4 hi = *(float4*)&stg[row * 128 + 64 + d];
            float4 c0 = *(const float4*)&rc[spos * DHEAD + d];
            float4 s0 = *(const float4*)&rs[spos * DHEAD + d];
            float4 c1 = *(const float4*)&rc[spos * DHEAD + 64 + d];
            float4 s1 = *(const float4*)&rs[spos * DHEAD + 64 + d];
            float l0 = (lo.x * c0.x - hi.x * s0.x) * qs;
            float l1 = (lo.y * c0.y - hi.y * s0.y) * qs;
            float l2 = (lo.z * c0.z - hi.z * s0.z) * qs;
            float l3 = (lo.w * c0.w - hi.w * s0.w) * qs;
            float u0 = (hi.x * c1.x + lo.x * s1.x) * qs;
            float u1 = (hi.y * c1.y + lo.y * s1.y) * qs;
            float u2 = (hi.z * c1.z + lo.z * s1.z) * qs;
            float u3 = (hi.w * c1.w + lo.w * s1.w) * qs;
            __half* Cp = C + (size_t)(m0 + row) * DMODEL + n0 + d;
            *(uint32_t*)&Cp[0]  = pk16(__float2half(l0), __float2half(l1));
            *(uint32_t*)&Cp[2]  = pk16(__float2half(l2), __float2half(l3));
            *(uint32_t*)&Cp[64] = pk16(__float2half(u0), __float2half(u1));
            *(uint32_t*)&Cp[66] = pk16(__float2half(u2), __float2half(u3));
        }
    }
}

// ============================================================================
// gemm_1p_f: plain fp16 GEMM, fp32 output (final projection). (R14 form)
// ============================================================================
__global__ __launch_bounds__(512)
void gemm_1p_f(const __half* __restrict__ A, const __half* __restrict__ B,
               float* __restrict__ C)
{
    GEMM1_BODY
#pragma unroll
    for (int i = 0; i < 2; i++)
#pragma unroll
        for (int j = 0; j < 4; j++) {
            int m = m0 + wm * 32 + i * 16 + (lane >> 2);
            int n = n0 + wn * 32 + j * 8 + (lane & 3) * 2;
            *(float2*)&C[(size_t)m * DMODEL + n]       = make_float2(acc[i][j][0], acc[i][j][1]);
            *(float2*)&C[(size_t)(m + 8) * DMODEL + n] = make_float2(acc[i][j][2], acc[i][j][3]);
        }
}

// ============================================================================
// attn_tc: flash attention, R16: 64 q-rows / 4 warps / 128 threads per CTA,
// 2 CTAs/SM (regs + smem fit). Grid 1024 CTAs.
// QK 1-product; PV 1-product; Q plane 16KB + 3 KV stages x 32KB = 112KB.
// ============================================================================
#define NKT (SEQ/64)
#define ATT_PLANE_B 16384
#define ATT_STAGE_B (2*ATT_PLANE_B)              // 32 KB
#define ATT_Q_B     16384                        // 64 rows x 256B
#define ATT_NSTAGE  3
#define ATT_TC_SMEM (ATT_Q_B + ATT_NSTAGE*ATT_STAGE_B)   // 114688

__global__ __launch_bounds__(128, 2)
void attn_tc(const __half* __restrict__ qh,
             const __half* __restrict__ khi,
             const __half* __restrict__ vhi,
             __half* __restrict__ oh)
{
    extern __shared__ char smc[];
    const uint32_t sb = smem_u32(smc);
    const uint32_t QH = sb;
    const uint32_t ST = sb + ATT_Q_B;

    const int tid = threadIdx.x;
    const int lane = tid & 31;
    const int wid = tid >> 5;          // 0..3
    const int b = blockIdx.z, h = blockIdx.y;
    const int q0 = blockIdx.x * 64;
    const int wrow = wid * 16;

    // ---- Q plane via cp.async (64 rows x 256B, swizzled) ----
    {
        const __half* src0 = qh + ((size_t)(b * SEQ + q0)) * DMODEL + h * DHEAD;
#pragma unroll
        for (int i = 0; i < 8; i++) {
            int idx = tid + i * 128;            // 0..1023 chunks
            int row = idx >> 4, ch = idx & 15;
            uint32_t dst = QH + row * 256 + ((ch ^ (row & 15)) << 4);
            CP_ASYNC16(dst, src0 + (size_t)row * DMODEL + ch * 8);
        }
    }

    const __half* pl[2] = { khi, vhi };
    auto load_kv = [&](int st, int kt) {
        uint32_t base = ST + st * ATT_STAGE_B;
#pragma unroll
        for (int i = 0; i < 16; i++) {
            int idx = tid + i * 128;           // 0..2047
            int p = idx >> 10;
            int c = idx & 1023;
            int row = c >> 4, ch = c & 15;
            const __half* src = pl[p] +
                ((size_t)(b * SEQ + kt * 64 + row)) * DMODEL + h * DHEAD + ch * 8;
            uint32_t dst = base + p * ATT_PLANE_B + row * 256 + ((ch ^ (row & 15)) << 4);
            CP_ASYNC16(dst, src);
        }
    };

    float o_[16][4];
#pragma unroll
    for (int n = 0; n < 16; n++)
#pragma unroll
        for (int r = 0; r < 4; r++) o_[n][r] = 0.f;
    float m_a = -3.0e38f, m_b = -3.0e38f, l_a = 0.f, l_b = 0.f;

    load_kv(0, 0); CP_COMMIT();
    load_kv(1, 1); CP_COMMIT();

    const int qrow = wrow + (lane & 15);
    const int lh = lane >> 4;

    int st = 0;
    for (int kt = 0; kt < NKT; kt++) {
        CP_WAIT(1);
        __syncthreads();
        uint32_t bs = ST + st * ATT_STAGE_B;

        if (kt + 2 < NKT) {
            int st2 = st + 2; if (st2 >= ATT_NSTAGE) st2 -= ATT_NSTAGE;
            load_kv(st2, kt + 2); CP_COMMIT();
        } else {
            CP_COMMIT();
        }

        // ---- scores: fp16 Q.K^T, fp32 accumulate ----
        float s[8][4];
#pragma unroll
        for (int j = 0; j < 8; j++)
#pragma unroll
            for (int r = 0; r < 4; r++) s[j][r] = 0.f;

#pragma unroll
        for (int ks = 0; ks < 8; ks++) {
            uint32_t qoff = (uint32_t)(qrow * 256 + (((ks * 2 + lh) ^ (qrow & 15)) << 4));
            uint32_t ah[4];
            LDSM4(ah[0], ah[1], ah[2], ah[3], QH + qoff);
#pragma unroll
            for (int nb = 0; nb < 4; nb++) {
                int krow = nb * 16 + (lane & 15);
                uint32_t koff = (uint32_t)(krow * 256 + (((ks * 2 + lh) ^ (krow & 15)) << 4));
                uint32_t h0, h1, h2, h3;
                LDSM4(h0, h1, h2, h3, bs + koff);
                uint32_t bh0[2] = { h0, h2 }, bh1[2] = { h1, h3 };
                MMA16816(s[2*nb],   ah, bh0);
                MMA16816(s[2*nb+1], ah, bh1);
            }
        }

        // ---- online softmax ----
        float mla = -3.0e38f, mlb = -3.0e38f;
#pragma unroll
        for (int j = 0; j < 8; j++) {
            mla = fmaxf(mla, fmaxf(s[j][0], s[j][1]));
            mlb = fmaxf(mlb, fmaxf(s[j][2], s[j][3]));
        }
        mla = fmaxf(mla, __shfl_xor_sync(0xffffffffu, mla, 1));
        mla = fmaxf(mla, __shfl_xor_sync(0xffffffffu, mla, 2));
        mlb = fmaxf(mlb, __shfl_xor_sync(0xffffffffu, mlb, 1));
        mlb = fmaxf(mlb, __shfl_xor_sync(0xffffffffu, mlb, 2));
        float mna = fmaxf(m_a, mla), mnb = fmaxf(m_b, mlb);
        float aa = __expf(m_a - mna), ab = __expf(m_b - mnb);

        uint32_t pAh[8], pBh[8];
        float sa = 0.f, sb2 = 0.f;
#pragma unroll
        for (int j = 0; j < 8; j++) {
            float p0 = __expf(s[j][0] - mna), p1 = __expf(s[j][1] - mna);
            float p2 = __expf(s[j][2] - mnb), p3 = __expf(s[j][3] - mnb);
            sa += p0 + p1; sb2 += p2 + p3;
            pAh[j] = pk16(__float2half(p0), __float2half(p1));
            pBh[j] = pk16(__float2half(p2), __float2half(p3));
        }
        sa  += __shfl_xor_sync(0xffffffffu, sa, 1);
        sa  += __shfl_xor_sync(0xffffffffu, sa, 2);
        sb2 += __shfl_xor_sync(0xffffffffu, sb2, 1);
        sb2 += __shfl_xor_sync(0xffffffffu, sb2, 2);
        m_a = mna; m_b = mnb;
        l_a = l_a * aa + sa; l_b = l_b * ab + sb2;

#pragma unroll
        for (int n = 0; n < 16; n++) {
            o_[n][0] *= aa; o_[n][1] *= aa; o_[n][2] *= ab; o_[n][3] *= ab;
        }

        // ---- PV: 1 product, V via ldmatrix.trans ----
#pragma unroll
        for (int kp = 0; kp < 4; kp++) {
            uint32_t ah4[4] = { pAh[2*kp], pBh[2*kp], pAh[2*kp+1], pBh[2*kp+1] };
            int vrow = kp * 16 + (lane & 15);
#pragma unroll
            for (int nb = 0; nb < 8; nb++) {
                uint32_t ch = (uint32_t)(nb * 2 + lh);
                uint32_t voff = (uint32_t)(vrow * 256 + ((ch ^ (vrow & 15)) << 4));
                uint32_t h0, h1, h2, h3;
                LDSM4T(h0, h1, h2, h3, bs + ATT_PLANE_B + voff);
                uint32_t bh0[2] = { h0, h1 }, bh1[2] = { h2, h3 };
                MMA16816(o_[2*nb],   ah4, bh0);
                MMA16816(o_[2*nb+1], ah4, bh1);
            }
        }

        if (++st == ATT_NSTAGE) st = 0;
    }

    // ---- epilogue: single fp16 att plane ----
    float ia = 1.f / l_a, ib = 1.f / l_b;
    size_t r0 = (size_t)(b * SEQ + q0 + wrow + (lane >> 2)) * DMODEL + h * DHEAD + 2 * (lane & 3);
    size_t r1 = r0 + (size_t)8 * DMODEL;
#pragma unroll
    for (int n = 0; n < 16; n++) {
        *(uint32_t*)&oh[r0 + n*8] = pk16(__float2half(o_[n][0] * ia), __float2half(o_[n][1] * ia));
        *(uint32_t*)&oh[r1 + n*8] = pk16(__float2half(o_[n][2] * ib), __float2half(o_[n][3] * ib));
    }
}

// ============================================================================
extern "C" void kernel_launch(void* const* d_in, const int* in_sizes, int n_in,
                              void* d_out, int out_size)
{
    const float* x  = (const float*)d_in[0];
    const float* rc = (const float*)d_in[1];
    const float* rs = (const float*)d_in[2];
    const float* Wq = (const float*)d_in[3];
    const float* Wk = (const float*)d_in[4];
    const float* Wv = (const float*)d_in[5];
    const float* Wo = (const float*)d_in[6];
    float* out = (float*)d_out;

    __half *xh, *wq, *wk, *wv, *wo, *qhp, *khp, *vhp, *att;
    cudaGetSymbolAddress((void**)&xh, g_xh);
    cudaGetSymbolAddress((void**)&wq, g_wq);     cudaGetSymbolAddress((void**)&wk, g_wk);
    cudaGetSymbolAddress((void**)&wv, g_wv);     cudaGetSymbolAddress((void**)&wo, g_wo);
    cudaGetSymbolAddress((void**)&qhp, g_qh);    cudaGetSymbolAddress((void**)&khp, g_kh);
    cudaGetSymbolAddress((void**)&vhp, g_vh);
    cudaGetSymbolAddress((void**)&att, g_att);

    cudaFuncSetAttribute(gemm_qkv,  cudaFuncAttributeMaxDynamicSharedMemorySize, G1_SMEM);
    cudaFuncSetAttribute(gemm_1p_f, cudaFuncAttributeMaxDynamicSharedMemorySize, G1_SMEM);
    cudaFuncSetAttribute(attn_tc,   cudaFuncAttributeMaxDynamicSharedMemorySize, ATT_TC_SMEM);

    pack_all<<<(NP_TOTAL + 1023) / 1024, 256>>>(
        x, Wq, Wk, Wv, Wo,
        (uint32_t*)xh, (uint32_t*)wq, (uint32_t*)wk, (uint32_t*)wv, (uint32_t*)wo);

    gemm_qkv<<<dim3(DMODEL / 128, MROWS / 128, 3), 512, G1_SMEM>>>(
        xh, wq, wk, wv, qhp, khp, vhp, rc, rs);

    attn_tc<<<dim3(SEQ / 64, NHEADS, BATCH), 128, ATT_TC_SMEM>>>(qhp, khp, vhp, att);

    gemm_1p_f<<<dim3(DMODEL / 128, MROWS / 128, 1), 512, G1_SMEM>>>(att, wo, out);
}

// round 17
// speedup vs baseline: 1.3208x; 1.1248x over previous
#include <cuda_runtime.h>
#include <cuda_fp16.h>
#include <math.h>
#include <stdint.h>

// Problem constants
#define BATCH 2
#define SEQ   2048
#define DMODEL 2048
#define NHEADS 16
#define DHEAD 128
#define MROWS (BATCH*SEQ)          // 4096
#define KDIM  DMODEL

// -------------------- scratch (static device globals; no allocation) ------
__device__ __align__(16) __half g_xh[MROWS * DMODEL];
__device__ __align__(16) __half g_wq[DMODEL * DMODEL];
__device__ __align__(16) __half g_wk[DMODEL * DMODEL];
__device__ __align__(16) __half g_wv[DMODEL * DMODEL];
__device__ __align__(16) __half g_wo[DMODEL * DMODEL];
__device__ __align__(16) __half g_qh[MROWS * DMODEL];
__device__ __align__(16) __half g_kh[MROWS * DMODEL];
__device__ __align__(16) __half g_vh[MROWS * DMODEL];
__device__ __align__(16) __half g_att[MROWS * DMODEL];

// ============================ PTX helpers ==================================
__device__ __forceinline__ uint32_t smem_u32(const void* p) {
    uint32_t a;
    asm("{ .reg .u64 t; cvta.to.shared.u64 t, %1; cvt.u32.u64 %0, t; }" : "=r"(a) : "l"(p));
    return a;
}
#define CP_ASYNC16(dst, src) \
    asm volatile("cp.async.cg.shared.global [%0], [%1], 16;" :: "r"(dst), "l"(src))
#define CP_COMMIT() asm volatile("cp.async.commit_group;" ::: "memory")
#define CP_WAIT(n)  asm volatile("cp.async.wait_group %0;" :: "n"(n) : "memory")

#define LDSM4(r0, r1, r2, r3, addr) \
    asm volatile("ldmatrix.sync.aligned.m8n8.x4.shared.b16 {%0,%1,%2,%3}, [%4];" \
        : "=r"(r0), "=r"(r1), "=r"(r2), "=r"(r3) : "r"(addr))
#define LDSM4T(r0, r1, r2, r3, addr) \
    asm volatile("ldmatrix.sync.aligned.m8n8.x4.trans.shared.b16 {%0,%1,%2,%3}, [%4];" \
        : "=r"(r0), "=r"(r1), "=r"(r2), "=r"(r3) : "r"(addr))

#define MMA16816(c, a, b) \
    asm volatile("mma.sync.aligned.m16n8k16.row.col.f32.f16.f16.f32 " \
        "{%0,%1,%2,%3},{%4,%5,%6,%7},{%8,%9},{%0,%1,%2,%3};" \
        : "+f"((c)[0]), "+f"((c)[1]), "+f"((c)[2]), "+f"((c)[3]) \
        : "r"((a)[0]), "r"((a)[1]), "r"((a)[2]), "r"((a)[3]), "r"((b)[0]), "r"((b)[1]))

__device__ __forceinline__ uint32_t pk16(__half a, __half b) {
    return (uint32_t)__half_as_ushort(a) | ((uint32_t)__half_as_ushort(b) << 16);
}

// ============================================================================
// pack_all: one launch converts x + 4 weights fp32->fp16; 4 pairs/thread.
// ============================================================================
#define NPX (MROWS * DMODEL / 2)
#define NPW (DMODEL * DMODEL / 2)
#define NP_TOTAL (NPX + 4 * NPW)

__global__ __launch_bounds__(256)
void pack_all(const float* __restrict__ x,
              const float* __restrict__ Wq, const float* __restrict__ Wk,
              const float* __restrict__ Wv, const float* __restrict__ Wo,
              uint32_t* __restrict__ xh,
              uint32_t* __restrict__ wq, uint32_t* __restrict__ wk,
              uint32_t* __restrict__ wv, uint32_t* __restrict__ wo)
{
    int i0 = blockIdx.x * 1024 + threadIdx.x;
#pragma unroll
    for (int t = 0; t < 4; t++) {
        int i = i0 + t * 256;
        if (i >= NP_TOTAL) return;
        const float* src; uint32_t* dst; int off;
        if (i < NPX)                { src = x;  dst = xh; off = i; }
        else if (i < NPX + NPW)     { src = Wq; dst = wq; off = i - NPX; }
        else if (i < NPX + 2*NPW)   { src = Wk; dst = wk; off = i - NPX - NPW; }
        else if (i < NPX + 3*NPW)   { src = Wv; dst = wv; off = i - NPX - 2*NPW; }
        else                        { src = Wo; dst = wo; off = i - NPX - 3*NPW; }
        float2 v = ((const float2*)src)[off];
        dst[off] = pk16(__float2half(v.x), __float2half(v.y));
    }
}

// ============================================================================
// gemm mainloop core (R17): CTA tile 64x128, 256 threads, 8 warps (2m x 4n),
// warp tile 32x32, BKD=64, 2 stages x 24KB (A 8KB + B 16KB). 3 CTAs/SM.
// ============================================================================
#define BKD 64
#define A_TILE_B (64 * BKD * 2)               // 8 KB
#define B_TILE_B (128 * BKD * 2)              // 16 KB
#define STG1_B   (A_TILE_B + B_TILE_B)        // 24 KB
#define G1_SMEM  (2 * STG1_B)                 // 48 KB (>= 32KB fp32 stage)

#define GEMM1_BODY                                                                   \
    extern __shared__ char smc[];                                                    \
    const uint32_t sb = smem_u32(smc);                                               \
    const int tid  = threadIdx.x;                                                    \
    const int lane = tid & 31;                                                       \
    const int wid  = tid >> 5;         /* 0..7 */                                    \
    const int wm   = wid & 1;          /* 2 m-tiles of 32 */                         \
    const int wn   = wid >> 1;         /* 4 n-tiles of 32 */                         \
    const int m0   = blockIdx.y * 64;                                                \
    const int n0   = blockIdx.x * 128;                                               \
    const int rL = tid >> 3, cL = tid & 7;                                           \
    const uint32_t dL = (uint32_t)(rL * 128 + ((cL ^ (rL & 7)) << 4));               \
    const int rH = (tid + 256) >> 3, cH = (tid + 256) & 7;                           \
    const uint32_t dH = (uint32_t)(rH * 128 + ((cH ^ (rH & 7)) << 4));               \
    const int rH2 = (tid + 512) >> 3, cH2 = (tid + 512) & 7;                         \
    const uint32_t dH2 = (uint32_t)(rH2 * 128 + ((cH2 ^ (rH2 & 7)) << 4));           \
    const int rH3 = (tid + 768) >> 3, cH3 = (tid + 768) & 7;                         \
    const uint32_t dH3 = (uint32_t)(rH3 * 128 + ((cH3 ^ (rH3 & 7)) << 4));           \
    const __half* srcA = A + (size_t)m0 * KDIM;                                      \
    const __half* srcB = B + (size_t)n0 * KDIM;                                      \
    auto load_stage = [&](int s, int kb) {                                           \
        uint32_t aBase = sb + s * STG1_B;                                            \
        uint32_t bBase = aBase + A_TILE_B;                                           \
        int koff = kb * BKD;                                                         \
        /* A: 512 chunks (64 rows x 8), 2/thread */                                  \
        CP_ASYNC16(aBase + dL, srcA + (size_t)rL * KDIM + koff + cL * 8);            \
        CP_ASYNC16(aBase + dH, srcA + (size_t)rH * KDIM + koff + cH * 8);            \
        /* B: 1024 chunks (128 rows x 8), 4/thread */                                \
        CP_ASYNC16(bBase + dL,  srcB + (size_t)rL  * KDIM + koff + cL  * 8);         \
        CP_ASYNC16(bBase + dH,  srcB + (size_t)rH  * KDIM + koff + cH  * 8);         \
        CP_ASYNC16(bBase + dH2, srcB + (size_t)rH2 * KDIM + koff + cH2 * 8);         \
        CP_ASYNC16(bBase + dH3, srcB + (size_t)rH3 * KDIM + koff + cH3 * 8);         \
    };                                                                               \
    float acc[2][4][4];                                                              \
    _Pragma("unroll")                                                                \
    for (int i = 0; i < 2; i++)                                                      \
        for (int j = 0; j < 4; j++)                                                  \
            for (int r = 0; r < 4; r++) acc[i][j][r] = 0.f;                          \
    load_stage(0, 0); CP_COMMIT();                                                   \
    const int arow = wm * 32 + (lane & 15);                                          \
    const int bnrow = wn * 32 + (lane & 15);                                         \
    const int lhalf = lane >> 4;                                                     \
    const int NKB = KDIM / BKD;                                                      \
    for (int kc = 0; kc < NKB; kc++) {                                               \
        if (kc + 1 < NKB) { load_stage((kc + 1) & 1, kc + 1); CP_COMMIT(); CP_WAIT(1); } \
        else              { CP_WAIT(0); }                                            \
        __syncthreads();                                                             \
        uint32_t aB = sb + (kc & 1) * STG1_B;                                        \
        uint32_t bB = aB + A_TILE_B;                                                 \
        _Pragma("unroll")                                                            \
        for (int ks = 0; ks < 4; ks++) {                                             \
            uint32_t ah[2][4], bh[4][2];                                             \
            _Pragma("unroll")                                                        \
            for (int i = 0; i < 2; i++) {                                            \
                int row = arow + i * 16;                                             \
                uint32_t off = (uint32_t)(row * 128 + (((ks * 2 + lhalf) ^ (row & 7)) << 4)); \
                LDSM4(ah[i][0], ah[i][1], ah[i][2], ah[i][3], aB + off);             \
            }                                                                        \
            _Pragma("unroll")                                                        \
            for (int jp = 0; jp < 2; jp++) {                                         \
                int row = bnrow + jp * 16;                                           \
                uint32_t off = (uint32_t)(row * 128 + (((ks * 2 + lhalf) ^ (row & 7)) << 4)); \
                uint32_t r0, r1_, r2_, r3_;                                          \
                LDSM4(r0, r1_, r2_, r3_, bB + off);                                  \
                bh[2 * jp][0] = r0;  bh[2 * jp][1] = r2_;                            \
                bh[2 * jp + 1][0] = r1_; bh[2 * jp + 1][1] = r3_;                    \
            }                                                                        \
            _Pragma("unroll")                                                        \
            for (int i = 0; i < 2; i++)                                              \
                for (int j = 0; j < 4; j++)                                          \
                    MMA16816(acc[i][j], ah[i], bh[j]);                               \
        }                                                                            \
        __syncthreads();                                                             \
    }

// ============================================================================
// gemm_qkv: QKV projection with rope fused into epilogue (fp32 staging 64x128).
// z==0: q (rope + 1/sqrt(dh)); z==1: k (rope); z==2: v (plain convert).
// ============================================================================
__global__ __launch_bounds__(256, 3)
void gemm_qkv(const __half* __restrict__ A,
              const __half* __restrict__ B0, const __half* __restrict__ B1,
              const __half* __restrict__ B2,
              __half* __restrict__ C0, __half* __restrict__ C1, __half* __restrict__ C2,
              const float* __restrict__ rc, const float* __restrict__ rs)
{
    const int z = blockIdx.z;
    const __half* B = (z == 0) ? B0 : (z == 1) ? B1 : B2;
    __half* C = (z == 0) ? C0 : (z == 1) ? C1 : C2;

    GEMM1_BODY

    // stage fp32 accumulators in (idle) pipeline smem: 64 x 128 fp32 = 32KB
    float* stg = (float*)smc;
#pragma unroll
    for (int i = 0; i < 2; i++)
#pragma unroll
        for (int j = 0; j < 4; j++) {
            int ml = wm * 32 + i * 16 + (lane >> 2);
            int nl = wn * 32 + j * 8 + (lane & 3) * 2;
            stg[ml * 128 + nl]           = acc[i][j][0];
            stg[ml * 128 + nl + 1]       = acc[i][j][1];
            stg[(ml + 8) * 128 + nl]     = acc[i][j][2];
            stg[(ml + 8) * 128 + nl + 1] = acc[i][j][3];
        }
    __syncthreads();

    if (z == 2) {
        // plain convert: 64*128/4 = 2048 float4 items, 8/thread
#pragma unroll
        for (int it = 0; it < 8; it++) {
            int idx = tid + it * 256;
            int row = idx >> 5;
            int q4 = (idx & 31) * 4;
            float4 v = *(float4*)&stg[row * 128 + q4];
            __half* Cp = C + (size_t)(m0 + row) * DMODEL + n0 + q4;
            *(uint32_t*)&Cp[0] = pk16(__float2half(v.x), __float2half(v.y));
            *(uint32_t*)&Cp[2] = pk16(__float2half(v.z), __float2half(v.w));
        }
    } else {
        const float qs = (z == 0) ? 0.088388347648318447f : 1.0f;
        // 64 rows x 16 lower-half quads = 1024 items, 4/thread
#pragma unroll
        for (int it = 0; it < 4; it++) {
            int idx = tid + it * 256;
            int row = idx >> 4;
            int d = (idx & 15) * 4;
            int spos = (m0 + row) & (SEQ - 1);
            float4 lo = *(float4*)&stg[row * 128 + d];
            float4 hi = *(float4*)&stg[row * 128 + 64 + d];
            float4 c0 = *(const float4*)&rc[spos * DHEAD + d];
            float4 s0 = *(const float4*)&rs[spos * DHEAD + d];
            float4 c1 = *(const float4*)&rc[spos * DHEAD + 64 + d];
            float4 s1 = *(const float4*)&rs[spos * DHEAD + 64 + d];
            float l0 = (lo.x * c0.x - hi.x * s0.x) * qs;
            float l1 = (lo.y * c0.y - hi.y * s0.y) * qs;
            float l2 = (lo.z * c0.z - hi.z * s0.z) * qs;
            float l3 = (lo.w * c0.w - hi.w * s0.w) * qs;
            float u0 = (hi.x * c1.x + lo.x * s1.x) * qs;
            float u1 = (hi.y * c1.y + lo.y * s1.y) * qs;
            float u2 = (hi.z * c1.z + lo.z * s1.z) * qs;
            float u3 = (hi.w * c1.w + lo.w * s1.w) * qs;
            __half* Cp = C + (size_t)(m0 + row) * DMODEL + n0 + d;
            *(uint32_t*)&Cp[0]  = pk16(__float2half(l0), __float2half(l1));
            *(uint32_t*)&Cp[2]  = pk16(__float2half(l2), __float2half(l3));
            *(uint32_t*)&Cp[64] = pk16(__float2half(u0), __float2half(u1));
            *(uint32_t*)&Cp[66] = pk16(__float2half(u2), __float2half(u3));
        }
    }
}

// ============================================================================
// gemm_1p_f: plain fp16 GEMM, fp32 output (final projection).
// ============================================================================
__global__ __launch_bounds__(256, 3)
void gemm_1p_f(const __half* __restrict__ A, const __half* __restrict__ B,
               float* __restrict__ C)
{
    GEMM1_BODY
#pragma unroll
    for (int i = 0; i < 2; i++)
#pragma unroll
        for (int j = 0; j < 4; j++) {
            int m = m0 + wm * 32 + i * 16 + (lane >> 2);
            int n = n0 + wn * 32 + j * 8 + (lane & 3) * 2;
            *(float2*)&C[(size_t)m * DMODEL + n]       = make_float2(acc[i][j][0], acc[i][j][1]);
            *(float2*)&C[(size_t)(m + 8) * DMODEL + n] = make_float2(acc[i][j][2], acc[i][j][3]);
        }
}

// ============================================================================
// attn_tc: flash attention (R16 form: 64 q-rows / 128 threads, 2 CTAs/SM).
// ============================================================================
#define NKT (SEQ/64)
#define ATT_PLANE_B 16384
#define ATT_STAGE_B (2*ATT_PLANE_B)              // 32 KB
#define ATT_Q_B     16384
#define ATT_NSTAGE  3
#define ATT_TC_SMEM (ATT_Q_B + ATT_NSTAGE*ATT_STAGE_B)   // 114688

__global__ __launch_bounds__(128, 2)
void attn_tc(const __half* __restrict__ qh,
             const __half* __restrict__ khi,
             const __half* __restrict__ vhi,
             __half* __restrict__ oh)
{
    extern __shared__ char smc[];
    const uint32_t sb = smem_u32(smc);
    const uint32_t QH = sb;
    const uint32_t ST = sb + ATT_Q_B;

    const int tid = threadIdx.x;
    const int lane = tid & 31;
    const int wid = tid >> 5;
    const int b = blockIdx.z, h = blockIdx.y;
    const int q0 = blockIdx.x * 64;
    const int wrow = wid * 16;

    {
        const __half* src0 = qh + ((size_t)(b * SEQ + q0)) * DMODEL + h * DHEAD;
#pragma unroll
        for (int i = 0; i < 8; i++) {
            int idx = tid + i * 128;
            int row = idx >> 4, ch = idx & 15;
            uint32_t dst = QH + row * 256 + ((ch ^ (row & 15)) << 4);
            CP_ASYNC16(dst, src0 + (size_t)row * DMODEL + ch * 8);
        }
    }

    const __half* pl[2] = { khi, vhi };
    auto load_kv = [&](int st, int kt) {
        uint32_t base = ST + st * ATT_STAGE_B;
#pragma unroll
        for (int i = 0; i < 16; i++) {
            int idx = tid + i * 128;
            int p = idx >> 10;
            int c = idx & 1023;
            int row = c >> 4, ch = c & 15;
            const __half* src = pl[p] +
                ((size_t)(b * SEQ + kt * 64 + row)) * DMODEL + h * DHEAD + ch * 8;
            uint32_t dst = base + p * ATT_PLANE_B + row * 256 + ((ch ^ (row & 15)) << 4);
            CP_ASYNC16(dst, src);
        }
    };

    float o_[16][4];
#pragma unroll
    for (int n = 0; n < 16; n++)
#pragma unroll
        for (int r = 0; r < 4; r++) o_[n][r] = 0.f;
    float m_a = -3.0e38f, m_b = -3.0e38f, l_a = 0.f, l_b = 0.f;

    load_kv(0, 0); CP_COMMIT();
    load_kv(1, 1); CP_COMMIT();

    const int qrow = wrow + (lane & 15);
    const int lh = lane >> 4;

    int st = 0;
    for (int kt = 0; kt < NKT; kt++) {
        CP_WAIT(1);
        __syncthreads();
        uint32_t bs = ST + st * ATT_STAGE_B;

        if (kt + 2 < NKT) {
            int st2 = st + 2; if (st2 >= ATT_NSTAGE) st2 -= ATT_NSTAGE;
            load_kv(st2, kt + 2); CP_COMMIT();
        } else {
            CP_COMMIT();
        }

        float s[8][4];
#pragma unroll
        for (int j = 0; j < 8; j++)
#pragma unroll
            for (int r = 0; r < 4; r++) s[j][r] = 0.f;

#pragma unroll
        for (int ks = 0; ks < 8; ks++) {
            uint32_t qoff = (uint32_t)(qrow * 256 + (((ks * 2 + lh) ^ (qrow & 15)) << 4));
            uint32_t ah[4];
            LDSM4(ah[0], ah[1], ah[2], ah[3], QH + qoff);
#pragma unroll
            for (int nb = 0; nb < 4; nb++) {
                int krow = nb * 16 + (lane & 15);
                uint32_t koff = (uint32_t)(krow * 256 + (((ks * 2 + lh) ^ (krow & 15)) << 4));
                uint32_t h0, h1, h2, h3;
                LDSM4(h0, h1, h2, h3, bs + koff);
                uint32_t bh0[2] = { h0, h2 }, bh1[2] = { h1, h3 };
                MMA16816(s[2*nb],   ah, bh0);
                MMA16816(s[2*nb+1], ah, bh1);
            }
        }

        float mla = -3.0e38f, mlb = -3.0e38f;
#pragma unroll
        for (int j = 0; j < 8; j++) {
            mla = fmaxf(mla, fmaxf(s[j][0], s[j][1]));
            mlb = fmaxf(mlb, fmaxf(s[j][2], s[j][3]));
        }
        mla = fmaxf(mla, __shfl_xor_sync(0xffffffffu, mla, 1));
        mla = fmaxf(mla, __shfl_xor_sync(0xffffffffu, mla, 2));
        mlb = fmaxf(mlb, __shfl_xor_sync(0xffffffffu, mlb, 1));
        mlb = fmaxf(mlb, __shfl_xor_sync(0xffffffffu, mlb, 2));
        float mna = fmaxf(m_a, mla), mnb = fmaxf(m_b, mlb);
        float aa = __expf(m_a - mna), ab = __expf(m_b - mnb);

        uint32_t pAh[8], pBh[8];
        float sa = 0.f, sb2 = 0.f;
#pragma unroll
        for (int j = 0; j < 8; j++) {
            float p0 = __expf(s[j][0] - mna), p1 = __expf(s[j][1] - mna);
            float p2 = __expf(s[j][2] - mnb), p3 = __expf(s[j][3] - mnb);
            sa += p0 + p1; sb2 += p2 + p3;
            pAh[j] = pk16(__float2half(p0), __float2half(p1));
            pBh[j] = pk16(__float2half(p2), __float2half(p3));
        }
        sa  += __shfl_xor_sync(0xffffffffu, sa, 1);
        sa  += __shfl_xor_sync(0xffffffffu, sa, 2);
        sb2 += __shfl_xor_sync(0xffffffffu, sb2, 1);
        sb2 += __shfl_xor_sync(0xffffffffu, sb2, 2);
        m_a = mna; m_b = mnb;
        l_a = l_a * aa + sa; l_b = l_b * ab + sb2;

#pragma unroll
        for (int n = 0; n < 16; n++) {
            o_[n][0] *= aa; o_[n][1] *= aa; o_[n][2] *= ab; o_[n][3] *= ab;
        }

#pragma unroll
        for (int kp = 0; kp < 4; kp++) {
            uint32_t ah4[4] = { pAh[2*kp], pBh[2*kp], pAh[2*kp+1], pBh[2*kp+1] };
            int vrow = kp * 16 + (lane & 15);
#pragma unroll
            for (int nb = 0; nb < 8; nb++) {
                uint32_t ch = (uint32_t)(nb * 2 + lh);
                uint32_t voff = (uint32_t)(vrow * 256 + ((ch ^ (vrow & 15)) << 4));
                uint32_t h0, h1, h2, h3;
                LDSM4T(h0, h1, h2, h3, bs + ATT_PLANE_B + voff);
                uint32_t bh0[2] = { h0, h1 }, bh1[2] = { h2, h3 };
                MMA16816(o_[2*nb],   ah4, bh0);
                MMA16816(o_[2*nb+1], ah4, bh1);
            }
        }

        if (++st == ATT_NSTAGE) st = 0;
    }

    float ia = 1.f / l_a, ib = 1.f / l_b;
    size_t r0 = (size_t)(b * SEQ + q0 + wrow + (lane >> 2)) * DMODEL + h * DHEAD + 2 * (lane & 3);
    size_t r1 = r0 + (size_t)8 * DMODEL;
#pragma unroll
    for (int n = 0; n < 16; n++) {
        *(uint32_t*)&oh[r0 + n*8] = pk16(__float2half(o_[n][0] * ia), __float2half(o_[n][1] * ia));
        *(uint32_t*)&oh[r1 + n*8] = pk16(__float2half(o_[n][2] * ib), __float2half(o_[n][3] * ib));
    }
}

// ============================================================================
extern "C" void kernel_launch(void* const* d_in, const int* in_sizes, int n_in,
                              void* d_out, int out_size)
{
    const float* x  = (const float*)d_in[0];
    const float* rc = (const float*)d_in[1];
    const float* rs = (const float*)d_in[2];
    const float* Wq = (const float*)d_in[3];
    const float* Wk = (const float*)d_in[4];
    const float* Wv = (const float*)d_in[5];
    const float* Wo = (const float*)d_in[6];
    float* out = (float*)d_out;

    __half *xh, *wq, *wk, *wv, *wo, *qhp, *khp, *vhp, *att;
    cudaGetSymbolAddress((void**)&xh, g_xh);
    cudaGetSymbolAddress((void**)&wq, g_wq);     cudaGetSymbolAddress((void**)&wk, g_wk);
    cudaGetSymbolAddress((void**)&wv, g_wv);     cudaGetSymbolAddress((void**)&wo, g_wo);
    cudaGetSymbolAddress((void**)&qhp, g_qh);    cudaGetSymbolAddress((void**)&khp, g_kh);
    cudaGetSymbolAddress((void**)&vhp, g_vh);
    cudaGetSymbolAddress((void**)&att, g_att);

    cudaFuncSetAttribute(gemm_qkv,  cudaFuncAttributeMaxDynamicSharedMemorySize, G1_SMEM);
    cudaFuncSetAttribute(gemm_1p_f, cudaFuncAttributeMaxDynamicSharedMemorySize, G1_SMEM);
    cudaFuncSetAttribute(attn_tc,   cudaFuncAttributeMaxDynamicSharedMemorySize, ATT_TC_SMEM);

    pack_all<<<(NP_TOTAL + 1023) / 1024, 256>>>(
        x, Wq, Wk, Wv, Wo,
        (uint32_t*)xh, (uint32_t*)wq, (uint32_t*)wk, (uint32_t*)wv, (uint32_t*)wo);

    gemm_qkv<<<dim3(DMODEL / 128, MROWS / 64, 3), 256, G1_SMEM>>>(
        xh, wq, wk, wv, qhp, khp, vhp, rc, rs);

    attn_tc<<<dim3(SEQ / 64, NHEADS, BATCH), 128, ATT_TC_SMEM>>>(qhp, khp, vhp, att);

    gemm_1p_f<<<dim3(DMODEL / 128, MROWS / 64, 1), 256, G1_SMEM>>>(att, wo, out);
}